// round 4
// baseline (speedup 1.0000x reference)
#include <cuda_runtime.h>

// img: [256, 3, 224, 224] f32, y_idx/x_idx: [256] i32.
// out[b,c,h,w] = img * (0 if h in [y,y+32) && w in [x,x+32) else 1)
//
// Persistent grid-stride streamer. Total float4 = 9,633,792 = 1176*256*32.
// Grid stride = 301,056 float4 = 24 planes = 8 batches exactly, so each
// thread's (h, w4) are loop-invariant and b advances by 8 per step.
// 4 groups x 8 front-batched float4 loads per thread, __ldcs/__stcs.

#define SQ 32
#define CH 3
#define HH 224
#define W4 56                      // 224/4 float4 per row
#define PLANE_F4 (HH * W4)         // 12544
#define NTHREADS 256
#define NBLOCKS 1176               // multiple of 49 -> stride is whole planes
#define STRIDE (NTHREADS * NBLOCKS) // 301056 f4 = 24 planes = 8 batches
#define GROUPS 4
#define MLP 8                      // 32 f4/thread total

__global__ __launch_bounds__(NTHREADS)
void random_square_dropout_kernel(const float4* __restrict__ img,
                                  const int* __restrict__ y_idx,
                                  const int* __restrict__ x_idx,
                                  float4* __restrict__ out) {
    const int tid = blockIdx.x * NTHREADS + threadIdx.x;   // 0..301055

    // Decompose once: loop-invariant geometry.
    const int plane = tid / PLANE_F4;        // 0..23
    const int rem   = tid % PLANE_F4;
    const int h     = rem / W4;
    const int w4    = rem % W4;
    const int b0    = plane / CH;            // 0..7
    const int w0    = w4 * 4;

    int idx = tid;
    int b   = b0;

#pragma unroll 1
    for (int g = 0; g < GROUPS; g++) {
        // Front-batch 8 independent float4 loads.
        float4 v[MLP];
#pragma unroll
        for (int j = 0; j < MLP; j++)
            v[j] = __ldcs(&img[idx + j * STRIDE]);

        // Mask: each j is a different batch (b + 8*j).
#pragma unroll
        for (int j = 0; j < MLP; j++) {
            const int bj = b + 8 * j;
            const int y  = __ldg(&y_idx[bj]);
            if ((unsigned)(h - y) < SQ) {
                const int x = __ldg(&x_idx[bj]);
                if ((unsigned)(w0     - x) < SQ) v[j].x = 0.f;
                if ((unsigned)(w0 + 1 - x) < SQ) v[j].y = 0.f;
                if ((unsigned)(w0 + 2 - x) < SQ) v[j].z = 0.f;
                if ((unsigned)(w0 + 3 - x) < SQ) v[j].w = 0.f;
            }
        }

#pragma unroll
        for (int j = 0; j < MLP; j++)
            __stcs(&out[idx + j * STRIDE], v[j]);

        idx += MLP * STRIDE;   // +64 batches worth of planes
        b   += 8 * MLP;
    }
}

extern "C" void kernel_launch(void* const* d_in, const int* in_sizes, int n_in,
                              void* d_out, int out_size) {
    const float4* img = (const float4*)d_in[0];
    const int* y_idx  = (const int*)d_in[1];
    const int* x_idx  = (const int*)d_in[2];
    float4* out       = (float4*)d_out;

    random_square_dropout_kernel<<<NBLOCKS, NTHREADS>>>(img, y_idx, x_idx, out);
}

// round 5
// speedup vs baseline: 1.0439x; 1.0439x over previous
#include <cuda_runtime.h>

// img: [256, 3, 224, 224] f32, y_idx/x_idx: [256] i32.
// out[b,c,h,w] = img * (0 if h in [y,y+32) && w in [x,x+32) else 1)
//
// R3 structure (tiled, MLP=8 front-batched float4 loads), but stores use
// DEFAULT cache policy: out is write-only and re-written every graph replay,
// so L2-resident dirty out-lines never touch DRAM. img reads stay __ldcs
// (evict-first) to avoid polluting L2.

#define SQ 32
#define BATCH 256
#define CH 3
#define HH 224
#define WW 224
#define W4 (WW / 4)                    // 56 float4 per row
#define TY 4                           // threads in y
#define RPT 8                          // rows per thread
#define TILE_H (TY * RPT)              // 32 rows per block

__global__ __launch_bounds__(W4 * TY)
void random_square_dropout_kernel(const float4* __restrict__ img,
                                  const int* __restrict__ y_idx,
                                  const int* __restrict__ x_idx,
                                  float4* __restrict__ out) {
    const int b  = blockIdx.z;
    const int c  = blockIdx.y;
    const int h0 = blockIdx.x * TILE_H + threadIdx.y;  // rows h0 + TY*k
    const int w4 = threadIdx.x;                        // 0..55

    const int y = __ldg(&y_idx[b]);
    const int x = __ldg(&x_idx[b]);

    const long plane = ((long)b * CH + c) * (long)(HH * W4);
    const long base  = plane + (long)h0 * W4 + w4;

    // Front-batched loads: 8 independent DRAM requests in flight per thread.
    float4 v[RPT];
#pragma unroll
    for (int k = 0; k < RPT; k++)
        v[k] = __ldcs(&img[base + (long)(k * TY) * W4]);

    // Column in-square flags (constant across this thread's rows).
    const int w0 = w4 * 4;
    const bool cx0 = (unsigned)(w0     - x) < SQ;
    const bool cx1 = (unsigned)(w0 + 1 - x) < SQ;
    const bool cx2 = (unsigned)(w0 + 2 - x) < SQ;
    const bool cx3 = (unsigned)(w0 + 3 - x) < SQ;

    if (cx0 || cx1 || cx2 || cx3) {
#pragma unroll
        for (int k = 0; k < RPT; k++) {
            const int h = h0 + k * TY;
            if ((unsigned)(h - y) < SQ) {
                if (cx0) v[k].x = 0.f;
                if (cx1) v[k].y = 0.f;
                if (cx2) v[k].z = 0.f;
                if (cx3) v[k].w = 0.f;
            }
        }
    }

    // Default-policy stores: let L2 retain dirty out-lines across replays.
#pragma unroll
    for (int k = 0; k < RPT; k++)
        out[base + (long)(k * TY) * W4] = v[k];
}

extern "C" void kernel_launch(void* const* d_in, const int* in_sizes, int n_in,
                              void* d_out, int out_size) {
    const float4* img = (const float4*)d_in[0];
    const int* y_idx  = (const int*)d_in[1];
    const int* x_idx  = (const int*)d_in[2];
    float4* out       = (float4*)d_out;

    dim3 block(W4, TY);                      // 56 x 4 = 224 threads
    dim3 grid(HH / TILE_H, CH, BATCH);       // 7 x 3 x 256 = 5376 blocks
    random_square_dropout_kernel<<<grid, block>>>(img, y_idx, x_idx, out);
}